// round 14
// baseline (speedup 1.0000x reference)
#include <cuda_runtime.h>
#include <cuda_bf16.h>
#include <math_constants.h>

#define NPARTS 24
#define MAXB   64
#define MAXN   16384
#define MAXC   128
#define XSLOTS 16    // xyz blocks per batch (2 warp-partials each -> 32 slots/batch)
#define NH     2     // n-halves per channel-pair in feat path
#define PACKB  256   // pack blocks at the head of the fused grid

// __device__ scratch (allocation-free per harness rules; zero-initialized)
__device__ unsigned int g_labels8[(MAXB * MAXN) / 4];   // u8-packed labels, 1 MB
// xyz partials, merge-coalesced layout: [b][k][slot 0..31][comp 0..3]
__device__ float g_partf[MAXB * NPARTS * 32 * 4];
// feat partials, merge-coalesced layout: [b][k][h][c]
__device__ float g_fsum[MAXB * NPARTS * NH * MAXC];
__device__ float g_fmax[MAXB * NPARTS * NH * MAXC];
// pack completion counter; reset to 0 by merge_kernel each replay
__device__ int   g_pack_done;

// ---------------------------------------------------------------------------
// fused: 64-thread blocks, 12 KB smem.
//   blocks [0, PACKB)            : pack labels -> u8 (full-machine parallel)
//   blocks [PACKB, +B*XSLOTS)    : xyz partial sums (raw labels, no wait)
//   blocks [PACKB+B*XSLOTS, ...) : R7 feat core — spin-waits on g_pack_done,
//                                  covered by xyz work in wave 1.
// Pack blocks have the lowest IDs -> always resident in wave 1 -> the feat
// spin cannot deadlock at any occupancy.
// ---------------------------------------------------------------------------
#define RMW1(f, k) do {                               \
    float2 _v = ap[(k) * 32];                         \
    _v.x += (f); _v.y = fmaxf(_v.y, (f));             \
    ap[(k) * 32] = _v;                                \
} while (0)

#define RMW4(f, q) do {                               \
    RMW1((f).x, (q) & 255);                           \
    RMW1((f).y, ((q) >> 8) & 255);                    \
    RMW1((f).z, ((q) >> 16) & 255);                   \
    RMW1((f).w, (q) >> 24);                           \
} while (0)

__global__ __launch_bounds__(64) void fused_kernel(
    const float* __restrict__ features, const float* __restrict__ xyz,
    const int* __restrict__ labels, int N, int C, int B)
{
    const int w    = threadIdx.x >> 5;
    const int lane = threadIdx.x & 31;

    __shared__ float4 acc4[2][NPARTS][16];            // 12 KB (all paths)

    if (blockIdx.x < PACKB) {
        // ---------------- pack path ----------------
        const int BN4 = (B * N) >> 2;
        const int T   = PACKB * 64;
        const int4* __restrict__ l4 = (const int4*)labels;
        for (int i = blockIdx.x * 64 + threadIdx.x; i < BN4; i += T) {
            const int4 li = l4[i];
            g_labels8[i] = (unsigned)li.x | ((unsigned)li.y << 8) |
                           ((unsigned)li.z << 16) | ((unsigned)li.w << 24);
        }
        __threadfence();                              // release stores
        __syncthreads();
        if (threadIdx.x == 0)
            atomicAdd(&g_pack_done, 1);
        return;
    }

    const int XYZB = B * XSLOTS;
    if (blockIdx.x < PACKB + XYZB) {
        // ---------------- xyz path (component scheme, raw labels) ----------
        const int g = lane >> 2;
        const int c = lane & 3;
        float* accf = (float*)&acc4[w][0][0];         // [k*64 + lane]
        #pragma unroll
        for (int k = 0; k < NPARTS; ++k)
            accf[k * 64 + lane] = 0.f;
        __syncwarp();

        const int xb    = blockIdx.x - PACKB;
        const int b     = xb / XSLOTS;
        const int s     = xb % XSLOTS;
        const int chunk = N / XSLOTS;                 // 1024 points per block
        const int base  = b * N + s * chunk + w * (chunk >> 1);
        const int iters = chunk >> 4;                 // 8 points per warp-iter

        // depth-2 prefetch
        int   pt   = base + g;
        int   lab0 = labels[pt];
        float v0   = (c < 3) ? xyz[3 * pt + c] : 1.0f;

        for (int i = 0; i < iters - 1; ++i) {
            const int ptn  = base + (i + 1) * 8 + g;
            const int   lab1 = labels[ptn];
            const float v1   = (c < 3) ? xyz[3 * ptn + c] : 1.0f;
            accf[lab0 * 64 + lane] += v0;
            lab0 = lab1; v0 = v1;
        }
        accf[lab0 * 64 + lane] += v0;
        __syncwarp();

        const int slotInB = s * 2 + w;                // 0..31 within batch
        for (int k = 0; k < NPARTS; ++k) {
            float v = accf[k * 64 + lane];
            v += __shfl_xor_sync(0xFFFFFFFFu, v, 4);
            v += __shfl_xor_sync(0xFFFFFFFFu, v, 8);
            v += __shfl_xor_sync(0xFFFFFFFFu, v, 16);
            if (lane < 4)   // [b][k][slot][comp] — merge reads this coalesced
                g_partf[(((size_t)(b * NPARTS + k)) * 32 + slotInB) * 4 + c] = v;
        }
        return;
    }

    // ---------------- feat path (R7 core) ----------------
    const int pair = lane >> 1;
    const int odd  = lane & 1;
    const int tasks_per_b = (C / 2) * NH;             // 128
    const int gwid = (blockIdx.x - PACKB - XYZB) * 2 + w;
    const int b  = gwid / tasks_per_b;
    const int r  = gwid % tasks_per_b;
    const int cp = r >> 1;                            // channel pair
    const int h  = r & 1;                             // n-half

    float2* ap = (float2*)((char*)(&acc4[w][0][0]) + pair * 16 + odd * 8);
    #pragma unroll
    for (int k = 0; k < NPARTS; ++k)
        ap[k * 32] = make_float2(0.f, -CUDART_INF_F);

    // wait for pack completion (covered by xyz blocks doing real work)
    if (threadIdx.x == 0) {
        while (*(volatile int*)&g_pack_done != PACKB)
            __nanosleep(128);
    }
    __syncthreads();
    __threadfence();                                  // acquire

    const int c = cp * 2 + odd;
    const float4* __restrict__ fr =
        (const float4*)features + ((size_t)(b * C + c) * (N >> 2));
    const unsigned* __restrict__ lr = g_labels8 + (((size_t)b * N) >> 2);

    const int half4 = N >> 3;                         // float4 words per half
    const int base  = h * half4;
    const int iters = half4 >> 4;                     // 16 words per warp-iter

    // depth-2 pipeline (R7-proven)
    float4   f0 = __ldcs(&fr[base + pair]);
    unsigned q0 = lr[base + pair];
    float4   f1 = __ldcs(&fr[base + 16 + pair]);
    unsigned q1 = lr[base + 16 + pair];

    for (int i = 0; i < iters - 2; ++i) {
        const int nb = base + (i + 2) * 16 + pair;
        const float4   f2 = __ldcs(&fr[nb]);
        const unsigned q2 = lr[nb];
        RMW4(f0, q0);
        f0 = f1; q0 = q1; f1 = f2; q1 = q2;
    }
    RMW4(f0, q0);
    RMW4(f1, q1);
    __syncwarp();

    for (int k = 0; k < NPARTS; ++k) {
        float2 v = ap[k * 32];
        #pragma unroll
        for (int off = 2; off < 32; off <<= 1) {
            v.x += __shfl_xor_sync(0xFFFFFFFFu, v.x, off);
            v.y = fmaxf(v.y, __shfl_xor_sync(0xFFFFFFFFu, v.y, off));
        }
        if (lane < 2) {  // lane0 = chan c, lane1 = chan c+1 totals
            const size_t idx = ((size_t)(b * NPARTS + k) * NH + h) * C + c;
            g_fsum[idx] = v.x;
            g_fmax[idx] = v.y;
        }
    }
}

// ---------------------------------------------------------------------------
// merge: one WARP per (b,k); all loads coalesced (R13 layout). Also resets
// g_pack_done for the next graph replay (stream order guarantees this runs
// before the next fused launch).
// ---------------------------------------------------------------------------
__global__ __launch_bounds__(256) void merge_kernel(
    float* __restrict__ out, int C, int B)
{
    if (blockIdx.x == 0 && threadIdx.x == 0)
        g_pack_done = 0;

    const int warp = (blockIdx.x * blockDim.x + threadIdx.x) >> 5;
    const int lane = threadIdx.x & 31;
    if (warp >= B * NPARTS) return;

    float4 v = *(const float4*)&g_partf[((size_t)warp * 32 + lane) * 4];
    #pragma unroll
    for (int off = 16; off; off >>= 1) {
        v.x += __shfl_xor_sync(0xFFFFFFFFu, v.x, off);
        v.y += __shfl_xor_sync(0xFFFFFFFFu, v.y, off);
        v.z += __shfl_xor_sync(0xFFFFFFFFu, v.z, off);
        v.w += __shfl_xor_sync(0xFFFFFFFFu, v.w, off);
    }
    const float denom = fmaxf(v.w, 1.f);

    const int outd = 3 + 2 * C;
    float* o = out + (size_t)warp * outd;
    if (lane == 0) {
        o[0] = v.x / denom;
        o[1] = v.y / denom;
        o[2] = v.z / denom;
    }

    const float* srow = &g_fsum[(size_t)warp * NH * C];
    const float* mrow = &g_fmax[(size_t)warp * NH * C];
    for (int c = lane; c < C; c += 32) {
        const float s0 = srow[c], s1 = srow[C + c];
        const float m0 = mrow[c], m1 = mrow[C + c];
        const float mean = (s0 + s1) / denom;
        o[3 + c]     = mean;
        o[3 + C + c] = fmaxf(fmaxf(m0, m1) - mean, 0.f);  // empty seg: -inf -> 0
    }
}

extern "C" void kernel_launch(void* const* d_in, const int* in_sizes, int n_in,
                              void* d_out, int out_size)
{
    const float* xyz      = (const float*)d_in[0];
    const float* features = (const float*)d_in[1];
    const int*   labels   = (const int*)d_in[2];
    float* out = (float*)d_out;

    const long long BN = in_sizes[2];                  // B*N
    const int C = (int)((long long)in_sizes[1] / BN);  // 128
    const int outd = 3 + 2 * C;                        // 259
    const int B = out_size / (NPARTS * outd);          // 64
    const int N = (int)(BN / B);                       // 16384

    const int xyz_blocks  = B * XSLOTS;                // 1024
    const int feat_blocks = B * (C / 2) * NH / 2;      // 4096
    fused_kernel<<<PACKB + xyz_blocks + feat_blocks, 64>>>(
        features, xyz, labels, N, C, B);

    merge_kernel<<<(B * NPARTS * 32 + 255) / 256, 256>>>(out, C, B);
}

// round 15
// speedup vs baseline: 1.0161x; 1.0161x over previous
#include <cuda_runtime.h>
#include <cuda_bf16.h>
#include <math_constants.h>

#define NPARTS 24
#define MAXB   64
#define MAXN   16384
#define MAXC   128
#define XSLOTS 16    // xyz blocks per batch (2 warp-partials each -> 32 slots/batch)
#define NH     2     // n-halves per channel-pair in feat path
#define PACKB  256   // pack blocks at the head of the fused grid

// __device__ scratch (allocation-free per harness rules; zero-initialized)
__device__ unsigned int g_labels8[(MAXB * MAXN) / 4];   // u8-packed labels, 1 MB
// xyz partials, merge-coalesced layout: [b][k][slot 0..31][comp 0..3]
__device__ float g_partf[MAXB * NPARTS * 32 * 4];
// feat partials, merge-coalesced layout: [b][k][h][c]
__device__ float g_fsum[MAXB * NPARTS * NH * MAXC];
__device__ float g_fmax[MAXB * NPARTS * NH * MAXC];
// pack completion counter; reset to 0 by merge_kernel each replay
__device__ int   g_pack_done;

// ---------------------------------------------------------------------------
// fused: 64-thread blocks, 12 KB smem.
//   blocks [0, PACKB)            : pack labels -> u8 (parallel, wave 1)
//   blocks [PACKB, +B*XSLOTS)    : xyz partial sums (raw labels, no wait)
//   blocks [PACKB+B*XSLOTS, ...) : R7 feat core — prefetches its first
//                                  feature loads, THEN spin-waits on pack.
// Pack blocks have the lowest IDs -> always resident in wave 1 -> no deadlock.
// ---------------------------------------------------------------------------
#define RMW1(f, k) do {                               \
    float2 _v = ap[(k) * 32];                         \
    _v.x += (f); _v.y = fmaxf(_v.y, (f));             \
    ap[(k) * 32] = _v;                                \
} while (0)

#define RMW4(f, q) do {                               \
    RMW1((f).x, (q) & 255);                           \
    RMW1((f).y, ((q) >> 8) & 255);                    \
    RMW1((f).z, ((q) >> 16) & 255);                   \
    RMW1((f).w, (q) >> 24);                           \
} while (0)

__global__ __launch_bounds__(64) void fused_kernel(
    const float* __restrict__ features, const float* __restrict__ xyz,
    const int* __restrict__ labels, int N, int C, int B)
{
    const int w    = threadIdx.x >> 5;
    const int lane = threadIdx.x & 31;

    __shared__ float4 acc4[2][NPARTS][16];            // 12 KB (all paths)

    if (blockIdx.x < PACKB) {
        // ---------------- pack path ----------------
        const int BN4 = (B * N) >> 2;
        const int T   = PACKB * 64;
        const int4* __restrict__ l4 = (const int4*)labels;
        for (int i = blockIdx.x * 64 + threadIdx.x; i < BN4; i += T) {
            const int4 li = l4[i];
            g_labels8[i] = (unsigned)li.x | ((unsigned)li.y << 8) |
                           ((unsigned)li.z << 16) | ((unsigned)li.w << 24);
        }
        __threadfence();                              // release stores
        __syncthreads();
        if (threadIdx.x == 0)
            atomicAdd(&g_pack_done, 1);
        return;
    }

    const int XYZB = B * XSLOTS;
    if (blockIdx.x < PACKB + XYZB) {
        // ---------------- xyz path (component scheme, raw labels) ----------
        const int g = lane >> 2;
        const int c = lane & 3;
        float* accf = (float*)&acc4[w][0][0];         // [k*64 + lane]
        #pragma unroll
        for (int k = 0; k < NPARTS; ++k)
            accf[k * 64 + lane] = 0.f;
        __syncwarp();

        const int xb    = blockIdx.x - PACKB;
        const int b     = xb / XSLOTS;
        const int s     = xb % XSLOTS;
        const int chunk = N / XSLOTS;                 // 1024 points per block
        const int base  = b * N + s * chunk + w * (chunk >> 1);
        const int iters = chunk >> 4;                 // 8 points per warp-iter

        // depth-2 prefetch
        int   pt   = base + g;
        int   lab0 = labels[pt];
        float v0   = (c < 3) ? xyz[3 * pt + c] : 1.0f;

        for (int i = 0; i < iters - 1; ++i) {
            const int ptn  = base + (i + 1) * 8 + g;
            const int   lab1 = labels[ptn];
            const float v1   = (c < 3) ? xyz[3 * ptn + c] : 1.0f;
            accf[lab0 * 64 + lane] += v0;
            lab0 = lab1; v0 = v1;
        }
        accf[lab0 * 64 + lane] += v0;
        __syncwarp();

        const int slotInB = s * 2 + w;                // 0..31 within batch
        for (int k = 0; k < NPARTS; ++k) {
            float v = accf[k * 64 + lane];
            v += __shfl_xor_sync(0xFFFFFFFFu, v, 4);
            v += __shfl_xor_sync(0xFFFFFFFFu, v, 8);
            v += __shfl_xor_sync(0xFFFFFFFFu, v, 16);
            if (lane < 4)   // [b][k][slot][comp] — merge reads this coalesced
                g_partf[(((size_t)(b * NPARTS + k)) * 32 + slotInB) * 4 + c] = v;
        }
        return;
    }

    // ---------------- feat path (R7 core) ----------------
    const int pair = lane >> 1;
    const int odd  = lane & 1;
    const int tasks_per_b = (C / 2) * NH;             // 128
    const int gwid = (blockIdx.x - PACKB - XYZB) * 2 + w;
    const int b  = gwid / tasks_per_b;
    const int r  = gwid % tasks_per_b;
    const int cp = r >> 1;                            // channel pair
    const int h  = r & 1;                             // n-half

    float2* ap = (float2*)((char*)(&acc4[w][0][0]) + pair * 16 + odd * 8);
    #pragma unroll
    for (int k = 0; k < NPARTS; ++k)
        ap[k * 32] = make_float2(0.f, -CUDART_INF_F);

    const int c = cp * 2 + odd;
    const float4* __restrict__ fr =
        (const float4*)features + ((size_t)(b * C + c) * (N >> 2));
    const unsigned* __restrict__ lr = g_labels8 + (((size_t)b * N) >> 2);

    const int half4 = N >> 3;                         // float4 words per half
    const int base  = h * half4;
    const int iters = half4 >> 4;                     // 16 words per warp-iter

    // prefetch the label-independent feature loads BEFORE the pack spin,
    // so the spin overlaps the first DRAM latency.
    float4 f0 = __ldcs(&fr[base + pair]);
    float4 f1 = __ldcs(&fr[base + 16 + pair]);

    // wait for pack completion (covered by xyz blocks + the loads above)
    if (threadIdx.x == 0) {
        while (*(volatile int*)&g_pack_done != PACKB)
            __nanosleep(128);
    }
    __syncthreads();
    __threadfence();                                  // acquire

    unsigned q0 = lr[base + pair];
    unsigned q1 = lr[base + 16 + pair];

    for (int i = 0; i < iters - 2; ++i) {
        const int nb = base + (i + 2) * 16 + pair;
        const float4   f2 = __ldcs(&fr[nb]);
        const unsigned q2 = lr[nb];
        RMW4(f0, q0);
        f0 = f1; q0 = q1; f1 = f2; q1 = q2;
    }
    RMW4(f0, q0);
    RMW4(f1, q1);
    __syncwarp();

    for (int k = 0; k < NPARTS; ++k) {
        float2 v = ap[k * 32];
        #pragma unroll
        for (int off = 2; off < 32; off <<= 1) {
            v.x += __shfl_xor_sync(0xFFFFFFFFu, v.x, off);
            v.y = fmaxf(v.y, __shfl_xor_sync(0xFFFFFFFFu, v.y, off));
        }
        if (lane < 2) {  // lane0 = chan c, lane1 = chan c+1 totals
            const size_t idx = ((size_t)(b * NPARTS + k) * NH + h) * C + c;
            g_fsum[idx] = v.x;
            g_fmax[idx] = v.y;
        }
    }
}

// ---------------------------------------------------------------------------
// merge: one 128-thread BLOCK per (b,k) — 8x the warp parallelism of R14.
// Each warp redundantly reduces the 32 xyz slots (one coalesced 512 B read),
// then warp w handles channels [32w, 32w+32): fully coalesced, no cross-warp
// dependencies. Also resets g_pack_done for the next graph replay.
// ---------------------------------------------------------------------------
__global__ __launch_bounds__(128) void merge_kernel(
    float* __restrict__ out, int C, int B)
{
    if (blockIdx.x == 0 && threadIdx.x == 0)
        g_pack_done = 0;

    const int bk   = blockIdx.x;                      // (b*NPARTS + k)
    const int w    = threadIdx.x >> 5;
    const int lane = threadIdx.x & 31;

    // redundant per-warp xyz reduction (32 slots = 32 lanes)
    float4 v = *(const float4*)&g_partf[((size_t)bk * 32 + lane) * 4];
    #pragma unroll
    for (int off = 16; off; off >>= 1) {
        v.x += __shfl_xor_sync(0xFFFFFFFFu, v.x, off);
        v.y += __shfl_xor_sync(0xFFFFFFFFu, v.y, off);
        v.z += __shfl_xor_sync(0xFFFFFFFFu, v.z, off);
        v.w += __shfl_xor_sync(0xFFFFFFFFu, v.w, off);
    }
    const float denom = fmaxf(v.w, 1.f);

    const int outd = 3 + 2 * C;
    float* o = out + (size_t)bk * outd;
    if (threadIdx.x == 0) {
        o[0] = v.x / denom;
        o[1] = v.y / denom;
        o[2] = v.z / denom;
    }

    const float* srow = &g_fsum[(size_t)bk * NH * C];
    const float* mrow = &g_fmax[(size_t)bk * NH * C];
    for (int c = w * 32 + lane; c < C; c += 128) {
        const float s0 = srow[c], s1 = srow[C + c];
        const float m0 = mrow[c], m1 = mrow[C + c];
        const float mean = (s0 + s1) / denom;
        o[3 + c]     = mean;
        o[3 + C + c] = fmaxf(fmaxf(m0, m1) - mean, 0.f);  // empty seg: -inf -> 0
    }
}

extern "C" void kernel_launch(void* const* d_in, const int* in_sizes, int n_in,
                              void* d_out, int out_size)
{
    const float* xyz      = (const float*)d_in[0];
    const float* features = (const float*)d_in[1];
    const int*   labels   = (const int*)d_in[2];
    float* out = (float*)d_out;

    const long long BN = in_sizes[2];                  // B*N
    const int C = (int)((long long)in_sizes[1] / BN);  // 128
    const int outd = 3 + 2 * C;                        // 259
    const int B = out_size / (NPARTS * outd);          // 64
    const int N = (int)(BN / B);                       // 16384

    const int xyz_blocks  = B * XSLOTS;                // 1024
    const int feat_blocks = B * (C / 2) * NH / 2;      // 4096
    fused_kernel<<<PACKB + xyz_blocks + feat_blocks, 64>>>(
        features, xyz, labels, N, C, B);

    merge_kernel<<<B * NPARTS, 128>>>(out, C, B);
}